// round 2
// baseline (speedup 1.0000x reference)
#include <cuda_runtime.h>
#include <cuda_bf16.h>
#include <math.h>

// ---------------- problem constants ----------------
#define NC 80
#define REG_MAX 16
#define NO 144            // 4*REG_MAX + NC
#define A_TOT 8400        // 6400 + 1600 + 400
#define PRE_TOPK 1000
#define MAX_DET 100
#define B_MAX 32
#define NBINS 4096
#define BCAP 1024         // boundary-list capacity

// ---------------- scratch (device globals; no allocation allowed) ----------------
__device__ float g_conf  [B_MAX * A_TOT];        // conf_m (-1 if <= 0.25)
__device__ int   g_cls   [B_MAX * A_TOT];
__device__ float g_box   [B_MAX * A_TOT * 4];    // xyxy
__device__ float g_topv  [B_MAX * PRE_TOPK];
__device__ int   g_topcls[B_MAX * PRE_TOPK];
__device__ float g_topbox[B_MAX * PRE_TOPK * 4];
__device__ float g_kept  [B_MAX * PRE_TOPK];

// ---------------- helpers ----------------
__device__ __forceinline__ unsigned f2key(float v) {
    unsigned u = __float_as_uint(v);
    return (u & 0x80000000u) ? ~u : (u | 0x80000000u);
}
__device__ __forceinline__ float key2f(unsigned k) {
    unsigned u = (k & 0x80000000u) ? (k & 0x7FFFFFFFu) : ~k;
    return __uint_as_float(u);
}
__device__ __forceinline__ int val2bin(float v) {
    float t = (v - 0.25f) * (4096.0f / 0.75f);
    int b = (int)t;
    if (b < 0) b = 0;
    if (b > NBINS - 1) b = NBINS - 1;
    return b;
}
// key desc, idx asc
__device__ __forceinline__ bool pair_before(unsigned ka, int ia, unsigned kb, int ib) {
    return (ka > kb) || (ka == kb && ia < ib);
}

// ---------------- kernel 1: decode ----------------
__global__ void decode_kernel(const float* __restrict__ p3,
                              const float* __restrict__ p4,
                              const float* __restrict__ p5)
{
    int a = blockIdx.x * blockDim.x + threadIdx.x;
    int b = blockIdx.y;
    if (a >= A_TOT) return;

    const float* src;
    int w, local;
    float stride;
    if (a < 6400)      { src = p3; w = 80; stride = 8.f;  local = a; }
    else if (a < 8000) { src = p4; w = 40; stride = 16.f; local = a - 6400; }
    else               { src = p5; w = 20; stride = 32.f; local = a - 8000; }

    int plane = w * w;
    int y = local / w;
    int x = local - y * w;
    const float* base = src + (size_t)b * NO * plane + y * w + x;

    // class max (sigmoid monotone -> argmax/max on logits)
    float best = -INFINITY;
    int bi = 0;
    #pragma unroll 4
    for (int c = 0; c < NC; ++c) {
        float v = base[(4 * REG_MAX + c) * plane];
        if (v > best) { best = v; bi = c; }
    }
    float conf = 1.0f / (1.0f + expf(-best));

    // DFL: softmax over 16 bins per side, expectation
    float d[4];
    #pragma unroll
    for (int k = 0; k < 4; ++k) {
        float lg[REG_MAX];
        float m = -INFINITY;
        #pragma unroll
        for (int r = 0; r < REG_MAX; ++r) {
            lg[r] = base[(k * REG_MAX + r) * plane];
            m = fmaxf(m, lg[r]);
        }
        float s = 0.f, dot = 0.f;
        #pragma unroll
        for (int r = 0; r < REG_MAX; ++r) {
            float e = expf(lg[r] - m);
            s += e;
            dot += e * (float)r;
        }
        d[k] = dot / s;
    }

    float xa = (float)x + 0.5f, ya = (float)y + 0.5f;
    float x1g = xa - d[0], y1g = ya - d[1];
    float x2g = xa + d[2], y2g = ya + d[3];
    float cx = (x1g + x2g) * 0.5f * stride;
    float cy = (y1g + y2g) * 0.5f * stride;
    float bw = (x2g - x1g) * stride;
    float bh = (y2g - y1g) * stride;

    int o = b * A_TOT + a;
    g_conf[o] = (conf > 0.25f) ? conf : -1.0f;
    g_cls[o]  = bi;
    g_box[o * 4 + 0] = cx - bw * 0.5f;
    g_box[o * 4 + 1] = cy - bh * 0.5f;
    g_box[o * 4 + 2] = cx + bw * 0.5f;
    g_box[o * 4 + 3] = cy + bh * 0.5f;
}

// ---------------- kernel 2: per-batch top-1000 (counting select + small sort) ----------------
__global__ void __launch_bounds__(1024) topk_kernel()
{
    __shared__ int      hist[NBINS];       // 16 KB
    __shared__ int      part[1024];        // 4 KB
    __shared__ unsigned candk[1024];       // 4 KB
    __shared__ int      candi[1024];       // 4 KB
    __shared__ unsigned bkey[BCAP];        // 4 KB
    __shared__ int      bidx[BCAP];        // 4 KB
    __shared__ int      s_cnt, s_bm, s_cross, s_greater;

    int b   = blockIdx.x;
    int tid = threadIdx.x;
    int lane = tid & 31;
    const float* conf = g_conf + b * A_TOT;

    for (int t = tid; t < NBINS; t += 1024) hist[t] = 0;
    if (tid == 0) { s_cnt = 0; s_bm = 0; s_cross = -1; s_greater = 0; }
    __syncthreads();

    // histogram
    const int PAD = 9216; // 9 * 1024 >= A_TOT
    for (int t = tid; t < PAD; t += 1024) {
        if (t < A_TOT) atomicAdd(&hist[val2bin(conf[t])], 1);
    }
    __syncthreads();

    // suffix scan over 4-bin groups
    {
        int g = hist[tid * 4] + hist[tid * 4 + 1] + hist[tid * 4 + 2] + hist[tid * 4 + 3];
        part[tid] = g;
        __syncthreads();
        for (int s = 1; s < 1024; s <<= 1) {
            int v = (tid + s < 1024) ? part[tid + s] : 0;
            __syncthreads();
            part[tid] += v;
            __syncthreads();
        }
        // find crossing bin: cumFromTop(c) >= K, cumFromTop(c+1) < K
        int above = (tid < 1023) ? part[tid + 1] : 0;  // sum of bins >= 4*(tid+1)
        for (int k = 3; k >= 0; --k) {
            int bin = tid * 4 + k;
            int cum = above + hist[bin];
            if (cum >= PRE_TOPK && above < PRE_TOPK) {
                s_cross = bin;
                s_greater = above;
            }
            above = cum;
        }
    }
    __syncthreads();

    int cross   = s_cross;
    int greater = s_greater;
    int needed  = PRE_TOPK - greater;

    // compaction: bins > cross -> cand; bins == cross -> boundary list
    for (int t = tid; t < PAD; t += 1024) {
        float v = (t < A_TOT) ? conf[t] : 0.f;
        int bin  = (t < A_TOT) ? val2bin(v) : -1;
        bool pg = (t < A_TOT) && (bin > cross);
        unsigned mg = __ballot_sync(0xFFFFFFFFu, pg);
        if (mg) {
            int leader = __ffs(mg) - 1;
            int base = 0;
            if (lane == leader) base = atomicAdd(&s_cnt, __popc(mg));
            base = __shfl_sync(0xFFFFFFFFu, base, leader);
            if (pg) {
                int pos = base + __popc(mg & ((1u << lane) - 1u));
                candk[pos] = f2key(v);
                candi[pos] = t;
            }
        }
        bool pe = (t < A_TOT) && (bin == cross);
        unsigned me = __ballot_sync(0xFFFFFFFFu, pe);
        if (me) {
            int leader = __ffs(me) - 1;
            int base = 0;
            if (lane == leader) base = atomicAdd(&s_bm, __popc(me));
            base = __shfl_sync(0xFFFFFFFFu, base, leader);
            if (pe) {
                int pos = base + __popc(me & ((1u << lane) - 1u));
                if (pos < BCAP) { bkey[pos] = f2key(v); bidx[pos] = t; }
            }
        }
    }
    __syncthreads();

    int m = s_bm;
    if (needed > 0) {
        if (m <= BCAP) {
            // exact rank selection among boundary elements
            for (int e = tid; e < m; e += 1024) {
                unsigned ke = bkey[e]; int ie = bidx[e];
                int rank = 0;
                for (int j = 0; j < m; ++j)
                    rank += pair_before(bkey[j], bidx[j], ke, ie) ? 1 : 0;
                if (rank < needed) {
                    int pos = atomicAdd(&s_cnt, 1);
                    candk[pos] = ke;
                    candi[pos] = ie;
                }
            }
        } else {
            // robust fallback (never expected on bench data)
            for (int i = tid; i < A_TOT; i += 1024) {
                float v = conf[i];
                if (val2bin(v) != cross) continue;
                unsigned ki = f2key(v);
                int rank = 0;
                for (int j = 0; j < A_TOT; ++j) {
                    float vj = conf[j];
                    if (val2bin(vj) != cross) continue;
                    unsigned kj = f2key(vj);
                    rank += pair_before(kj, j, ki, i) ? 1 : 0;
                }
                if (rank < needed) {
                    int pos = atomicAdd(&s_cnt, 1);
                    candk[pos] = ki;
                    candi[pos] = i;
                }
            }
        }
    }
    __syncthreads();

    // pad to 1024 and bitonic sort (key desc, idx asc)
    if (tid >= PRE_TOPK) { candk[tid] = 0u; candi[tid] = 0x7FFFFFFF; }
    __syncthreads();

    for (int k = 2; k <= 1024; k <<= 1) {
        for (int j = k >> 1; j > 0; j >>= 1) {
            int ixj = tid ^ j;
            if (ixj > tid) {
                bool desc = ((tid & k) == 0);
                unsigned ka = candk[tid], kb = candk[ixj];
                int      ia = candi[tid], ib = candi[ixj];
                bool sw = desc ? pair_before(kb, ib, ka, ia)
                               : pair_before(ka, ia, kb, ib);
                if (sw) {
                    candk[tid] = kb; candi[tid] = ib;
                    candk[ixj] = ka; candi[ixj] = ia;
                }
            }
            __syncthreads();
        }
    }

    // gather outputs
    if (tid < PRE_TOPK) {
        int si = candi[tid];
        g_topv[b * PRE_TOPK + tid]   = key2f(candk[tid]);
        g_topcls[b * PRE_TOPK + tid] = g_cls[b * A_TOT + si];
        int src = (b * A_TOT + si) * 4;
        int dst = (b * PRE_TOPK + tid) * 4;
        g_topbox[dst + 0] = g_box[src + 0];
        g_topbox[dst + 1] = g_box[src + 1];
        g_topbox[dst + 2] = g_box[src + 2];
        g_topbox[dst + 3] = g_box[src + 3];
    }
}

// ---------------- kernel 3: NMS (chunked IoU bitmask + warp-serial scan) ----------------
#define NMS_CHUNK 64
#define NMS_WORDS 16   // ceil(1000/64)

__global__ void __launch_bounds__(1024) nms_kernel()
{
    __shared__ float bx1[PRE_TOPK], by1[PRE_TOPK], bx2[PRE_TOPK], by2[PRE_TOPK];
    __shared__ float cf[PRE_TOPK];
    __shared__ unsigned long long chunkmask[NMS_CHUNK * NMS_WORDS]; // 8 KB
    __shared__ unsigned char keep[PRE_TOPK];

    int b = blockIdx.x;
    int tid = threadIdx.x;

    for (int t = tid; t < PRE_TOPK; t += 1024) {
        int o = (b * PRE_TOPK + t) * 4;
        bx1[t] = g_topbox[o + 0];
        by1[t] = g_topbox[o + 1];
        bx2[t] = g_topbox[o + 2];
        by2[t] = g_topbox[o + 3];
        cf[t]  = g_topv[b * PRE_TOPK + t];
    }
    __syncthreads();

    unsigned long long rem = 0ull;  // warp0 lane l owns removed word l

    for (int c0 = 0; c0 < PRE_TOPK; c0 += NMS_CHUNK) {
        // fill mask rows for i in [c0, c0+64)
        for (int task = tid; task < NMS_CHUNK * NMS_WORDS; task += 1024) {
            int i  = c0 + (task >> 4);
            int wd = task & 15;
            unsigned long long mword = 0ull;
            if (i < PRE_TOPK) {
                float ax1 = bx1[i], ay1 = by1[i], ax2 = bx2[i], ay2 = by2[i];
                float areaA = (ax2 - ax1) * (ay2 - ay1);
                int j0 = wd * 64;
                int jend = min(j0 + 64, PRE_TOPK);
                for (int j = max(j0, i + 1); j < jend; ++j) {
                    float ix1 = fmaxf(ax1, bx1[j]);
                    float iy1 = fmaxf(ay1, by1[j]);
                    float ix2 = fminf(ax2, bx2[j]);
                    float iy2 = fminf(ay2, by2[j]);
                    float iw = fmaxf(ix2 - ix1, 0.f);
                    float ih = fmaxf(iy2 - iy1, 0.f);
                    float inter = iw * ih;
                    float areaB = (bx2[j] - bx1[j]) * (by2[j] - by1[j]);
                    float iou = inter / (areaA + areaB - inter + 1e-7f);
                    if (iou > 0.45f) mword |= (1ull << (j - j0));
                }
            }
            chunkmask[task] = mword;
        }
        __syncthreads();

        // warp 0: serial greedy scan for this chunk
        if (tid < 32) {
            int lane = tid;
            int iend = min(c0 + NMS_CHUNK, PRE_TOPK);
            for (int i = c0; i < iend; ++i) {
                int w = i >> 6;
                int kf = 0;
                if (lane == w)
                    kf = (cf[i] > 0.f) && !((rem >> (i & 63)) & 1ull);
                kf = __shfl_sync(0xFFFFFFFFu, kf, w);
                if (kf && lane < NMS_WORDS)
                    rem |= chunkmask[(i - c0) * NMS_WORDS + lane];
                if (lane == 0) keep[i] = (unsigned char)kf;
            }
        }
        __syncthreads();
    }

    for (int t = tid; t < PRE_TOPK; t += 1024)
        g_kept[b * PRE_TOPK + t] = keep[t] ? cf[t] : -1.0f;
}

// ---------------- kernel 4: final top-100 + output assembly ----------------
__global__ void final_kernel(float* __restrict__ out, int B)
{
    __shared__ float v[1024];
    __shared__ int   id[1024];
    __shared__ int   cnt;
    int b = blockIdx.x;
    int tid = threadIdx.x;

    for (int t = tid; t < 1024; t += blockDim.x) {
        if (t < PRE_TOPK) { v[t] = g_kept[b * PRE_TOPK + t]; id[t] = t; }
        else              { v[t] = -INFINITY;                id[t] = 0x7FFFFFFF; }
    }
    if (tid == 0) cnt = 0;
    __syncthreads();

    for (int k = 2; k <= 1024; k <<= 1) {
        for (int j = k >> 1; j > 0; j >>= 1) {
            for (int t = tid; t < 1024; t += blockDim.x) {
                int ixj = t ^ j;
                if (ixj > t) {
                    bool desc = ((t & k) == 0);
                    float va = v[t],  vb = v[ixj];
                    int   ia = id[t], ib = id[ixj];
                    bool before_ab = (va > vb) || (va == vb && ia < ib);
                    bool sw = desc ? !before_ab : before_ab;
                    // careful: need swap when out of order for the direction
                    if (desc ? ((vb > va) || (vb == va && ib < ia))
                             : ((va > vb) || (va == vb && ia < ib))) {
                        v[t] = vb; id[t] = ib;
                        v[ixj] = va; id[ixj] = ia;
                    }
                    (void)sw; (void)before_ab;
                }
            }
            __syncthreads();
        }
    }

    // output layout: [num_dets (B)] [boxes (B*100*4)] [scores (B*100)] [classes (B*100)]
    float* o_num = out;
    float* o_box = out + B;
    float* o_sc  = out + B + B * MAX_DET * 4;
    float* o_cl  = out + B + B * MAX_DET * 5;

    for (int t = tid; t < MAX_DET; t += blockDim.x) {
        float dv = v[t];
        bool valid = dv > 0.f;
        int di = id[t];
        o_sc[b * MAX_DET + t] = valid ? dv : 0.f;
        int dst = (b * MAX_DET + t) * 4;
        if (valid) {
            int src = (b * PRE_TOPK + di) * 4;
            o_box[dst + 0] = g_topbox[src + 0];
            o_box[dst + 1] = g_topbox[src + 1];
            o_box[dst + 2] = g_topbox[src + 2];
            o_box[dst + 3] = g_topbox[src + 3];
            o_cl[b * MAX_DET + t] = (float)g_topcls[b * PRE_TOPK + di];
            atomicAdd(&cnt, 1);
        } else {
            o_box[dst + 0] = 0.f;
            o_box[dst + 1] = 0.f;
            o_box[dst + 2] = 0.f;
            o_box[dst + 3] = 0.f;
            o_cl[b * MAX_DET + t] = 0.f;
        }
    }
    __syncthreads();
    if (tid == 0) o_num[b] = (float)cnt;
}

// ---------------- launcher ----------------
extern "C" void kernel_launch(void* const* d_in, const int* in_sizes, int n_in,
                              void* d_out, int out_size)
{
    const float* p3 = (const float*)d_in[0];
    const float* p4 = (const float*)d_in[1];
    const float* p5 = (const float*)d_in[2];
    int B = in_sizes[0] / (NO * 80 * 80);
    if (B > B_MAX) B = B_MAX;

    dim3 g1((A_TOT + 255) / 256, B);
    decode_kernel<<<g1, 256>>>(p3, p4, p5);
    topk_kernel<<<B, 1024>>>();
    nms_kernel<<<B, 1024>>>();
    final_kernel<<<B, 256>>>((float*)d_out, B);
}

// round 4
// speedup vs baseline: 1.0723x; 1.0723x over previous
#include <cuda_runtime.h>
#include <cuda_bf16.h>
#include <math.h>

// ---------------- problem constants ----------------
#define NC 80
#define REG_MAX 16
#define NO 144            // 4*REG_MAX + NC
#define A_TOT 8400        // 6400 + 1600 + 400
#define PRE_TOPK 1000
#define MAX_DET 100
#define B_MAX 32
#define NBINS 4096

// ---------------- scratch (device globals; no allocation allowed) ----------------
__device__ float  g_conf[B_MAX * A_TOT];     // conf_m (-1 if <= 0.25)
__device__ int    g_cls [B_MAX * A_TOT];
__device__ float4 g_box [B_MAX * A_TOT];     // xyxy

// ---------------- helpers ----------------
__device__ __forceinline__ unsigned f2key(float v) {
    unsigned u = __float_as_uint(v);
    return (u & 0x80000000u) ? ~u : (u | 0x80000000u);
}
__device__ __forceinline__ float key2f(unsigned k) {
    unsigned u = (k & 0x80000000u) ? (k & 0x7FFFFFFFu) : ~k;
    return __uint_as_float(u);
}
__device__ __forceinline__ int val2bin(float v) {
    float t = (v - 0.25f) * (4096.0f / 0.75f);
    int b = (int)t;
    if (b < 0) b = 0;
    if (b > NBINS - 1) b = NBINS - 1;
    return b;
}
// packed sort key: value desc, index asc on ties
__device__ __forceinline__ unsigned long long packkey(float v, int idx) {
    return ((unsigned long long)f2key(v) << 32) |
           (unsigned long long)(0xFFFFFFFFu - (unsigned)idx);
}

// ---------------- kernel 1: decode (identical math to passing round-2 version) ----------------
__global__ void __launch_bounds__(256) decode_kernel(const float* __restrict__ p3,
                                                     const float* __restrict__ p4,
                                                     const float* __restrict__ p5)
{
    int a = blockIdx.x * blockDim.x + threadIdx.x;
    int b = blockIdx.y;
    if (a >= A_TOT) return;

    const float* src;
    int w, local;
    float stride;
    if (a < 6400)      { src = p3; w = 80; stride = 8.f;  local = a; }
    else if (a < 8000) { src = p4; w = 40; stride = 16.f; local = a - 6400; }
    else               { src = p5; w = 20; stride = 32.f; local = a - 8000; }

    int plane = w * w;
    int y = local / w;
    int x = local - y * w;
    const float* base = src + (size_t)b * NO * plane + y * w + x;

    // class max (sigmoid monotone -> argmax/max on logits)
    float best = -INFINITY;
    int bi = 0;
    #pragma unroll 4
    for (int c = 0; c < NC; ++c) {
        float v = base[(4 * REG_MAX + c) * plane];
        if (v > best) { best = v; bi = c; }
    }
    float conf = 1.0f / (1.0f + expf(-best));

    // DFL: softmax over 16 bins per side, expectation
    float d[4];
    #pragma unroll
    for (int k = 0; k < 4; ++k) {
        float lg[REG_MAX];
        float m = -INFINITY;
        #pragma unroll
        for (int r = 0; r < REG_MAX; ++r) {
            lg[r] = base[(k * REG_MAX + r) * plane];
            m = fmaxf(m, lg[r]);
        }
        float s = 0.f, dot = 0.f;
        #pragma unroll
        for (int r = 0; r < REG_MAX; ++r) {
            float e = expf(lg[r] - m);
            s += e;
            dot += e * (float)r;
        }
        d[k] = dot / s;
    }

    float xa = (float)x + 0.5f, ya = (float)y + 0.5f;
    float x1g = xa - d[0], y1g = ya - d[1];
    float x2g = xa + d[2], y2g = ya + d[3];
    float cx = (x1g + x2g) * 0.5f * stride;
    float cy = (y1g + y2g) * 0.5f * stride;
    float bw = (x2g - x1g) * stride;
    float bh = (y2g - y1g) * stride;

    int o = b * A_TOT + a;
    g_conf[o] = (conf > 0.25f) ? conf : -1.0f;
    g_cls[o]  = bi;
    g_box[o] = make_float4(cx - bw * 0.5f, cy - bh * 0.5f,
                           cx + bw * 0.5f, cy + bh * 0.5f);
}

// ---------------- kernel 2: fused topk + NMS + final (one block per batch) ----------------
#define NMS_CHUNK 64
#define NMS_WORDS 16   // ceil(1000/64)
#define SM_BYTES 37120

__global__ void __launch_bounds__(1024) fused_kernel(float* __restrict__ out, int B)
{
    __shared__ __align__(16) char sm[SM_BYTES];
    // phase-1 views
    int*                hist  = (int*)sm;                                // [4096] 16KB
    unsigned long long* blist = (unsigned long long*)(sm + 20480);       // [1024] 8KB
    unsigned long long* cand  = (unsigned long long*)(sm + 28672);       // [1024] 8KB
    // phase-2 views (aliased after barriers)
    float* bx1 = (float*)(sm + 0);
    float* by1 = (float*)(sm + 4000);
    float* bx2 = (float*)(sm + 8000);
    float* by2 = (float*)(sm + 12000);
    float* cf  = (float*)(sm + 16000);                                   // [1000]
    int*   candi = (int*)(sm + 20480);                                   // [1024]
    unsigned char* keep = (unsigned char*)(sm + 24576);                  // [1000]
    unsigned long long* chunkmask = (unsigned long long*)(sm + 28672);   // [1024]
    int*   detsrc = (int*)(sm + 28672);                                  // [100] (after NMS)
    int*   ctr = (int*)(sm + 36864);                                     // [8]
    int*   ws  = ctr + 8;                                                // [32]

    int b    = blockIdx.x;
    int tid  = threadIdx.x;
    int lane = tid & 31;
    int wid  = tid >> 5;
    const float* conf = g_conf + b * A_TOT;

    // ---------- phase 1a: histogram ----------
    for (int t = tid; t < NBINS; t += 1024) hist[t] = 0;
    if (tid == 0) { ctr[0] = 0; ctr[1] = 0; ctr[2] = 0; ctr[3] = 0; ctr[4] = 0; }
    __syncthreads();
    for (int t = tid; t < A_TOT; t += 1024)
        atomicAdd(&hist[val2bin(conf[t])], 1);
    __syncthreads();

    // ---------- phase 1b: suffix scan (shfl-based, 2 barriers) ----------
    int g = hist[4 * tid] + hist[4 * tid + 1] + hist[4 * tid + 2] + hist[4 * tid + 3];
    int s = g;  // in-warp inclusive suffix sum
    #pragma unroll
    for (int o = 1; o < 32; o <<= 1) {
        int v = __shfl_down_sync(0xFFFFFFFFu, s, o);
        if (lane + o < 32) s += v;
    }
    if (lane == 0) ws[wid] = s;   // warp total
    __syncthreads();
    if (wid == 0) {
        int v = ws[lane];
        int t2 = v;
        #pragma unroll
        for (int o = 1; o < 32; o <<= 1) {
            int u = __shfl_down_sync(0xFFFFFFFFu, t2, o);
            if (lane + o < 32) t2 += u;
        }
        ws[lane] = t2 - v;        // exclusive suffix: sum of warps > lane
    }
    __syncthreads();
    {
        int above = ws[wid] + (s - g);   // sum over 4-bin groups strictly after this one
        #pragma unroll
        for (int k = 3; k >= 0; --k) {
            int bin = 4 * tid + k;
            int cum = above + hist[bin];
            if (cum >= PRE_TOPK && above < PRE_TOPK) { ctr[2] = bin; ctr[3] = above; }
            above = cum;
        }
    }
    __syncthreads();
    int cross   = ctr[2];
    int greater = ctr[3];
    int needed  = PRE_TOPK - greater;

    // ---------- phase 1c: compaction (bins > cross -> cand; == cross -> blist) ----------
    for (int t = tid; t < 9216; t += 1024) {    // 9*1024 >= A_TOT, uniform warps
        bool in = t < A_TOT;
        float v = in ? conf[t] : 0.f;
        int bin = in ? val2bin(v) : -1;
        bool pg = in && (bin > cross);
        unsigned mg = __ballot_sync(0xFFFFFFFFu, pg);
        if (mg) {
            int leader = __ffs(mg) - 1;
            int base = 0;
            if (lane == leader) base = atomicAdd(&ctr[0], __popc(mg));
            base = __shfl_sync(0xFFFFFFFFu, base, leader);
            if (pg) cand[base + __popc(mg & ((1u << lane) - 1u))] = packkey(v, t);
        }
        bool pe = in && (bin == cross);
        unsigned me = __ballot_sync(0xFFFFFFFFu, pe);
        if (me) {
            int leader = __ffs(me) - 1;
            int base = 0;
            if (lane == leader) base = atomicAdd(&ctr[1], __popc(me));
            base = __shfl_sync(0xFFFFFFFFu, base, leader);
            if (pe) {
                int pos = base + __popc(me & ((1u << lane) - 1u));
                if (pos < 1024) blist[pos] = packkey(v, t);
            }
        }
    }
    __syncthreads();

    // ---------- phase 1d: boundary rank selection ----------
    int m = ctr[1];
    if (needed > 0) {
        if (m <= 1024) {
            for (int e = tid; e < m; e += 1024) {
                unsigned long long ke = blist[e];
                int rank = 0;
                for (int j = 0; j < m; ++j) rank += (blist[j] > ke) ? 1 : 0;
                if (rank < needed) cand[atomicAdd(&ctr[0], 1)] = ke;
            }
        } else {
            // robust fallback (not expected on bench data)
            for (int i = tid; i < A_TOT; i += 1024) {
                float v = conf[i];
                if (val2bin(v) != cross) continue;
                unsigned long long ki = packkey(v, i);
                int rank = 0;
                for (int j = 0; j < A_TOT; ++j) {
                    float vj = conf[j];
                    if (val2bin(vj) != cross) continue;
                    rank += (packkey(vj, j) > ki) ? 1 : 0;
                }
                if (rank < needed) cand[atomicAdd(&ctr[0], 1)] = ki;
            }
        }
    }
    __syncthreads();

    // ---------- phase 1e: pad + bitonic sort desc (packed u64) ----------
    if (tid >= PRE_TOPK) cand[tid] = 0ull;
    __syncthreads();
    for (int k = 2; k <= 1024; k <<= 1) {
        for (int j = k >> 1; j > 0; j >>= 1) {
            int ixj = tid ^ j;
            if (ixj > tid) {
                unsigned long long a = cand[tid], c = cand[ixj];
                bool desc = ((tid & k) == 0);
                if (desc ? (c > a) : (a > c)) { cand[tid] = c; cand[ixj] = a; }
            }
            __syncthreads();
        }
    }

    // ---------- phase transition: extract sorted list, gather boxes ----------
    float l_cf = 0.f; int l_si = 0; float4 l_bb = make_float4(0, 0, 0, 0);
    if (tid < PRE_TOPK) {
        unsigned long long kk = cand[tid];
        l_si = (int)(0xFFFFFFFFu - (unsigned)kk);
        l_cf = key2f((unsigned)(kk >> 32));
        l_bb = g_box[b * A_TOT + l_si];
    }
    __syncthreads();  // cand read done; hist/blist regions free to alias
    if (tid < PRE_TOPK) {
        candi[tid] = l_si;
        cf[tid]    = l_cf;
        bx1[tid] = l_bb.x; by1[tid] = l_bb.y;
        bx2[tid] = l_bb.z; by2[tid] = l_bb.w;
    }
    __syncthreads();

    // ---------- phase 2: NMS (chunked IoU bitmask + warp-serial greedy) ----------
    unsigned long long rem = 0ull;   // warp0 lane l owns removed-word l
    for (int c0 = 0; c0 < PRE_TOPK; c0 += NMS_CHUNK) {
        for (int task = tid; task < NMS_CHUNK * NMS_WORDS; task += 1024) {
            int i  = c0 + (task >> 4);
            int wd = task & 15;
            unsigned long long mword = 0ull;
            if (i < PRE_TOPK) {
                float ax1 = bx1[i], ay1 = by1[i], ax2 = bx2[i], ay2 = by2[i];
                float areaA = (ax2 - ax1) * (ay2 - ay1);
                int j0 = wd * 64;
                int jend = min(j0 + 64, PRE_TOPK);
                for (int j = max(j0, i + 1); j < jend; ++j) {
                    float ix1 = fmaxf(ax1, bx1[j]);
                    float iy1 = fmaxf(ay1, by1[j]);
                    float ix2 = fminf(ax2, bx2[j]);
                    float iy2 = fminf(ay2, by2[j]);
                    float iw = fmaxf(ix2 - ix1, 0.f);
                    float ih = fmaxf(iy2 - iy1, 0.f);
                    float inter = iw * ih;
                    float areaB = (bx2[j] - bx1[j]) * (by2[j] - by1[j]);
                    float iou = inter / (areaA + areaB - inter + 1e-7f);
                    if (iou > 0.45f) mword |= (1ull << (j - j0));
                }
            }
            chunkmask[task] = mword;
        }
        __syncthreads();

        if (tid < 32) {
            int iend = min(c0 + NMS_CHUNK, PRE_TOPK);
            for (int i = c0; i < iend; ++i) {
                int w = i >> 6;
                int kf = 0;
                if (lane == w)
                    kf = (cf[i] > 0.f) && !((rem >> (i & 63)) & 1ull);
                kf = __shfl_sync(0xFFFFFFFFu, kf, w);
                if (kf && lane < NMS_WORDS)
                    rem |= chunkmask[(i - c0) * NMS_WORDS + lane];
                if (lane == 0) keep[i] = (unsigned char)kf;
            }
        }
        __syncthreads();
    }

    // ---------- phase 3: final top-100 = order-preserving compaction of kept ----------
    // cf is descending, kept values > 0 > -1 fillers, ties resolved by index asc:
    // top_k(where(keep, cf, -1), 100) == stable compaction of keep==1 entries.
    int kflag = (tid < PRE_TOPK) ? (int)keep[tid] : 0;
    unsigned mk = __ballot_sync(0xFFFFFFFFu, kflag != 0);
    int lanepre = __popc(mk & ((1u << lane) - 1u));
    if (lane == 0) ws[wid] = __popc(mk);
    __syncthreads();
    if (wid == 0) {
        int v = ws[lane];
        int p = v;
        #pragma unroll
        for (int o = 1; o < 32; o <<= 1) {
            int u = __shfl_up_sync(0xFFFFFFFFu, p, o);
            if (lane >= o) p += u;
        }
        ws[lane] = p - v;                 // exclusive prefix
        if (lane == 31) ctr[4] = p;       // total kept
    }
    __syncthreads();
    int pos = ws[wid] + lanepre;
    if (kflag && pos < MAX_DET) detsrc[pos] = tid;   // aliases chunkmask (NMS done)
    __syncthreads();
    int ndet = min(ctr[4], MAX_DET);

    // ---------- phase 4: output assembly ----------
    // layout: [num_dets (B)] [boxes (B*100*4)] [scores (B*100)] [classes (B*100)]
    float* o_num = out;
    float* o_box = out + B;
    float* o_sc  = out + B + B * MAX_DET * 4;
    float* o_cl  = out + B + B * MAX_DET * 5;

    if (tid < MAX_DET) {
        bool valid = tid < ndet;
        int sp = valid ? detsrc[tid] : 0;
        o_sc[b * MAX_DET + tid] = valid ? cf[sp] : 0.f;
        float4 bb = valid ? make_float4(bx1[sp], by1[sp], bx2[sp], by2[sp])
                          : make_float4(0.f, 0.f, 0.f, 0.f);
        ((float4*)o_box)[b * MAX_DET + tid] = bb;
        o_cl[b * MAX_DET + tid] = valid ? (float)g_cls[b * A_TOT + candi[sp]] : 0.f;
    }
    if (tid == 0) o_num[b] = (float)ndet;
}

// ---------------- launcher ----------------
extern "C" void kernel_launch(void* const* d_in, const int* in_sizes, int n_in,
                              void* d_out, int out_size)
{
    const float* p3 = (const float*)d_in[0];
    const float* p4 = (const float*)d_in[1];
    const float* p5 = (const float*)d_in[2];
    int B = in_sizes[0] / (NO * 80 * 80);
    if (B > B_MAX) B = B_MAX;

    dim3 g1((A_TOT + 255) / 256, B);
    decode_kernel<<<g1, 256>>>(p3, p4, p5);
    fused_kernel<<<B, 1024>>>((float*)d_out, B);
}

// round 6
// speedup vs baseline: 2.1892x; 2.0416x over previous
#include <cuda_runtime.h>
#include <cuda_bf16.h>
#include <math.h>

// ---------------- problem constants ----------------
#define NC 80
#define REG_MAX 16
#define NO 144            // 4*REG_MAX + NC
#define A_TOT 8400        // 6400 + 1600 + 400
#define PRE_TOPK 1000
#define MAX_DET 100
#define B_MAX 32
#define NBINS 4096
#define NMS_CHUNK 64
#define NMS_WORDS 16      // ceil(1000/64)
#define NMS_NCHUNKS 16    // ceil(1000/64)

// ---------------- scratch (device globals; no allocation allowed) ----------------
__device__ float  g_conf[B_MAX * A_TOT];                 // conf_m (-1 if <= 0.25)
__device__ int    g_cls [B_MAX * A_TOT];
__device__ float4 g_box [B_MAX * A_TOT];                 // xyxy
__device__ float  g_scf [B_MAX * PRE_TOPK];              // sorted conf (desc)
__device__ float4 g_sbox[B_MAX * PRE_TOPK];              // sorted boxes
__device__ int    g_scls[B_MAX * PRE_TOPK];              // sorted classes
__device__ unsigned long long g_mask[B_MAX * PRE_TOPK * NMS_WORDS]; // 4 MB IoU masks

// ---------------- helpers ----------------
__device__ __forceinline__ unsigned f2key(float v) {
    unsigned u = __float_as_uint(v);
    return (u & 0x80000000u) ? ~u : (u | 0x80000000u);
}
__device__ __forceinline__ float key2f(unsigned k) {
    unsigned u = (k & 0x80000000u) ? (k & 0x7FFFFFFFu) : ~k;
    return __uint_as_float(u);
}
__device__ __forceinline__ int val2bin(float v) {
    float t = (v - 0.25f) * (4096.0f / 0.75f);
    int b = (int)t;
    if (b < 0) b = 0;
    if (b > NBINS - 1) b = NBINS - 1;
    return b;
}
// packed sort key: value desc, index asc on ties
__device__ __forceinline__ unsigned long long packkey(float v, int idx) {
    return ((unsigned long long)f2key(v) << 32) |
           (unsigned long long)(0xFFFFFFFFu - (unsigned)idx);
}

// ---------------- kernel 1: decode (identical math to passing rounds) ----------------
__global__ void __launch_bounds__(256) decode_kernel(const float* __restrict__ p3,
                                                     const float* __restrict__ p4,
                                                     const float* __restrict__ p5)
{
    int a = blockIdx.x * blockDim.x + threadIdx.x;
    int b = blockIdx.y;
    if (a >= A_TOT) return;

    const float* src;
    int w, local;
    float stride;
    if (a < 6400)      { src = p3; w = 80; stride = 8.f;  local = a; }
    else if (a < 8000) { src = p4; w = 40; stride = 16.f; local = a - 6400; }
    else               { src = p5; w = 20; stride = 32.f; local = a - 8000; }

    int plane = w * w;
    int y = local / w;
    int x = local - y * w;
    const float* base = src + (size_t)b * NO * plane + y * w + x;

    float best = -INFINITY;
    int bi = 0;
    #pragma unroll 4
    for (int c = 0; c < NC; ++c) {
        float v = base[(4 * REG_MAX + c) * plane];
        if (v > best) { best = v; bi = c; }
    }
    float conf = 1.0f / (1.0f + expf(-best));

    float d[4];
    #pragma unroll
    for (int k = 0; k < 4; ++k) {
        float lg[REG_MAX];
        float m = -INFINITY;
        #pragma unroll
        for (int r = 0; r < REG_MAX; ++r) {
            lg[r] = base[(k * REG_MAX + r) * plane];
            m = fmaxf(m, lg[r]);
        }
        float s = 0.f, dot = 0.f;
        #pragma unroll
        for (int r = 0; r < REG_MAX; ++r) {
            float e = expf(lg[r] - m);
            s += e;
            dot += e * (float)r;
        }
        d[k] = dot / s;
    }

    float xa = (float)x + 0.5f, ya = (float)y + 0.5f;
    float x1g = xa - d[0], y1g = ya - d[1];
    float x2g = xa + d[2], y2g = ya + d[3];
    float cx = (x1g + x2g) * 0.5f * stride;
    float cy = (y1g + y2g) * 0.5f * stride;
    float bw = (x2g - x1g) * stride;
    float bh = (y2g - y1g) * stride;

    int o = b * A_TOT + a;
    g_conf[o] = (conf > 0.25f) ? conf : -1.0f;
    g_cls[o]  = bi;
    g_box[o] = make_float4(cx - bw * 0.5f, cy - bh * 0.5f,
                           cx + bw * 0.5f, cy + bh * 0.5f);
}

// ---------------- kernel 2: per-batch top-1000 select + sort ----------------
#define SM_BYTES 37120

__global__ void __launch_bounds__(1024) topk_kernel()
{
    __shared__ __align__(16) char sm[SM_BYTES];
    int*                hist  = (int*)sm;                                // [4096] 16KB
    unsigned long long* blist = (unsigned long long*)(sm + 20480);       // [1024] 8KB
    unsigned long long* cand  = (unsigned long long*)(sm + 28672);       // [1024] 8KB
    int*   ctr = (int*)(sm + 36864);                                     // [8]
    int*   ws  = ctr + 8;                                                // [32]

    int b    = blockIdx.x;
    int tid  = threadIdx.x;
    int lane = tid & 31;
    int wid  = tid >> 5;
    const float* conf = g_conf + b * A_TOT;

    // histogram
    for (int t = tid; t < NBINS; t += 1024) hist[t] = 0;
    if (tid == 0) { ctr[0] = 0; ctr[1] = 0; ctr[2] = 0; ctr[3] = 0; }
    __syncthreads();
    for (int t = tid; t < A_TOT; t += 1024)
        atomicAdd(&hist[val2bin(conf[t])], 1);
    __syncthreads();

    // suffix scan (shfl-based)
    int g = hist[4 * tid] + hist[4 * tid + 1] + hist[4 * tid + 2] + hist[4 * tid + 3];
    int s = g;
    #pragma unroll
    for (int o = 1; o < 32; o <<= 1) {
        int v = __shfl_down_sync(0xFFFFFFFFu, s, o);
        if (lane + o < 32) s += v;
    }
    if (lane == 0) ws[wid] = s;
    __syncthreads();
    if (wid == 0) {
        int v = ws[lane];
        int t2 = v;
        #pragma unroll
        for (int o = 1; o < 32; o <<= 1) {
            int u = __shfl_down_sync(0xFFFFFFFFu, t2, o);
            if (lane + o < 32) t2 += u;
        }
        ws[lane] = t2 - v;
    }
    __syncthreads();
    {
        int above = ws[wid] + (s - g);
        #pragma unroll
        for (int k = 3; k >= 0; --k) {
            int bin = 4 * tid + k;
            int cum = above + hist[bin];
            if (cum >= PRE_TOPK && above < PRE_TOPK) { ctr[2] = bin; ctr[3] = above; }
            above = cum;
        }
    }
    __syncthreads();
    int cross   = ctr[2];
    int greater = ctr[3];
    int needed  = PRE_TOPK - greater;

    // compaction
    for (int t = tid; t < 9216; t += 1024) {
        bool in = t < A_TOT;
        float v = in ? conf[t] : 0.f;
        int bin = in ? val2bin(v) : -1;
        bool pg = in && (bin > cross);
        unsigned mg = __ballot_sync(0xFFFFFFFFu, pg);
        if (mg) {
            int leader = __ffs(mg) - 1;
            int base = 0;
            if (lane == leader) base = atomicAdd(&ctr[0], __popc(mg));
            base = __shfl_sync(0xFFFFFFFFu, base, leader);
            if (pg) cand[base + __popc(mg & ((1u << lane) - 1u))] = packkey(v, t);
        }
        bool pe = in && (bin == cross);
        unsigned me = __ballot_sync(0xFFFFFFFFu, pe);
        if (me) {
            int leader = __ffs(me) - 1;
            int base = 0;
            if (lane == leader) base = atomicAdd(&ctr[1], __popc(me));
            base = __shfl_sync(0xFFFFFFFFu, base, leader);
            if (pe) {
                int pos = base + __popc(me & ((1u << lane) - 1u));
                if (pos < 1024) blist[pos] = packkey(v, t);
            }
        }
    }
    __syncthreads();

    // boundary rank selection
    int m = ctr[1];
    if (needed > 0) {
        if (m <= 1024) {
            for (int e = tid; e < m; e += 1024) {
                unsigned long long ke = blist[e];
                int rank = 0;
                for (int j = 0; j < m; ++j) rank += (blist[j] > ke) ? 1 : 0;
                if (rank < needed) cand[atomicAdd(&ctr[0], 1)] = ke;
            }
        } else {
            for (int i = tid; i < A_TOT; i += 1024) {
                float v = conf[i];
                if (val2bin(v) != cross) continue;
                unsigned long long ki = packkey(v, i);
                int rank = 0;
                for (int j = 0; j < A_TOT; ++j) {
                    float vj = conf[j];
                    if (val2bin(vj) != cross) continue;
                    rank += (packkey(vj, j) > ki) ? 1 : 0;
                }
                if (rank < needed) cand[atomicAdd(&ctr[0], 1)] = ki;
            }
        }
    }
    __syncthreads();

    // pad + bitonic sort desc (packed u64)
    if (tid >= PRE_TOPK) cand[tid] = 0ull;
    __syncthreads();
    for (int k = 2; k <= 1024; k <<= 1) {
        for (int j = k >> 1; j > 0; j >>= 1) {
            int ixj = tid ^ j;
            if (ixj > tid) {
                unsigned long long a = cand[tid], c = cand[ixj];
                bool desc = ((tid & k) == 0);
                if (desc ? (c > a) : (a > c)) { cand[tid] = c; cand[ixj] = a; }
            }
            __syncthreads();
        }
    }

    // emit sorted list to global
    if (tid < PRE_TOPK) {
        unsigned long long kk = cand[tid];
        int si = (int)(0xFFFFFFFFu - (unsigned)kk);
        g_scf[b * PRE_TOPK + tid]  = key2f((unsigned)(kk >> 32));
        g_sbox[b * PRE_TOPK + tid] = g_box[b * A_TOT + si];
        g_scls[b * PRE_TOPK + tid] = g_cls[b * A_TOT + si];
    }
}

// ---------------- kernel 3: IoU mask fill (whole-chip parallel) ----------------
__global__ void __launch_bounds__(1024) maskfill_kernel()
{
    __shared__ float bx1[PRE_TOPK], by1[PRE_TOPK], bx2[PRE_TOPK], by2[PRE_TOPK];
    int c  = blockIdx.x;   // chunk 0..15
    int b  = blockIdx.y;   // batch
    int tid = threadIdx.x;

    for (int t = tid; t < PRE_TOPK; t += 1024) {
        float4 bb = g_sbox[b * PRE_TOPK + t];
        bx1[t] = bb.x; by1[t] = bb.y; bx2[t] = bb.z; by2[t] = bb.w;
    }
    __syncthreads();

    int i  = c * NMS_CHUNK + (tid >> 4);
    int wd = tid & 15;
    if (i >= PRE_TOPK) return;

    float ax1 = bx1[i], ay1 = by1[i], ax2 = bx2[i], ay2 = by2[i];
    float areaA = (ax2 - ax1) * (ay2 - ay1);
    unsigned long long mword = 0ull;
    int j0 = wd * 64;
    int jend = min(j0 + 64, PRE_TOPK);
    for (int j = max(j0, i + 1); j < jend; ++j) {
        float ix1 = fmaxf(ax1, bx1[j]);
        float iy1 = fmaxf(ay1, by1[j]);
        float ix2 = fminf(ax2, bx2[j]);
        float iy2 = fminf(ay2, by2[j]);
        float iw = fmaxf(ix2 - ix1, 0.f);
        float ih = fmaxf(iy2 - iy1, 0.f);
        float inter = iw * ih;
        float areaB = (bx2[j] - bx1[j]) * (by2[j] - by1[j]);
        float iou = inter / (areaA + areaB - inter + 1e-7f);
        if (iou > 0.45f) mword |= (1ull << (j - j0));
    }
    g_mask[(b * PRE_TOPK + i) * NMS_WORDS + wd] = mword;
}

// ---------------- kernel 4: greedy scan + top-100 compaction + output ----------------
__global__ void __launch_bounds__(1024) scanout_kernel(float* __restrict__ out, int B)
{
    __shared__ float cf[PRE_TOPK];
    __shared__ unsigned long long chunkmask[NMS_CHUNK * NMS_WORDS];  // 8 KB
    __shared__ unsigned char keep[PRE_TOPK];
    __shared__ int detsrc[MAX_DET];
    __shared__ int ws[32];
    __shared__ int s_total;

    int b    = blockIdx.x;
    int tid  = threadIdx.x;
    int lane = tid & 31;
    int wid  = tid >> 5;

    for (int t = tid; t < PRE_TOPK; t += 1024)
        cf[t] = g_scf[b * PRE_TOPK + t];
    __syncthreads();

    unsigned long long rem = 0ull;   // warp0 lane l owns removed-word l
    const unsigned long long* gm = g_mask + (size_t)b * PRE_TOPK * NMS_WORDS;

    for (int c0 = 0; c0 < PRE_TOPK; c0 += NMS_CHUNK) {
        int base = c0 * NMS_WORDS;
        int navail = min(NMS_CHUNK, PRE_TOPK - c0) * NMS_WORDS;
        if (tid < navail) chunkmask[tid] = gm[base + tid];
        __syncthreads();

        if (tid < 32) {
            int iend = min(c0 + NMS_CHUNK, PRE_TOPK);
            for (int i = c0; i < iend; ++i) {
                int w = i >> 6;
                int kf = 0;
                if (lane == w)
                    kf = (cf[i] > 0.f) && !((rem >> (i & 63)) & 1ull);
                kf = __shfl_sync(0xFFFFFFFFu, kf, w);
                if (kf && lane < NMS_WORDS)
                    rem |= chunkmask[(i - c0) * NMS_WORDS + lane];
                if (lane == 0) keep[i] = (unsigned char)kf;
            }
        }
        __syncthreads();
    }

    // top-100 = order-preserving compaction of kept (cf desc, stable ties)
    int kflag = (tid < PRE_TOPK) ? (int)keep[tid] : 0;
    unsigned mk = __ballot_sync(0xFFFFFFFFu, kflag != 0);
    int lanepre = __popc(mk & ((1u << lane) - 1u));
    if (lane == 0) ws[wid] = __popc(mk);
    __syncthreads();
    if (wid == 0) {
        int v = ws[lane];
        int p = v;
        #pragma unroll
        for (int o = 1; o < 32; o <<= 1) {
            int u = __shfl_up_sync(0xFFFFFFFFu, p, o);
            if (lane >= o) p += u;
        }
        ws[lane] = p - v;
        if (lane == 31) s_total = p;
    }
    __syncthreads();
    int pos = ws[wid] + lanepre;
    if (kflag && pos < MAX_DET) detsrc[pos] = tid;
    __syncthreads();
    int ndet = min(s_total, MAX_DET);

    // output: [num_dets (B)] [boxes (B*100*4)] [scores (B*100)] [classes (B*100)]
    float* o_num = out;
    float* o_box = out + B;
    float* o_sc  = out + B + B * MAX_DET * 4;
    float* o_cl  = out + B + B * MAX_DET * 5;

    if (tid < MAX_DET) {
        bool valid = tid < ndet;
        int sp = valid ? detsrc[tid] : 0;
        o_sc[b * MAX_DET + tid] = valid ? cf[sp] : 0.f;
        float4 bb = valid ? g_sbox[b * PRE_TOPK + sp]
                          : make_float4(0.f, 0.f, 0.f, 0.f);
        ((float4*)o_box)[b * MAX_DET + tid] = bb;
        o_cl[b * MAX_DET + tid] = valid ? (float)g_scls[b * PRE_TOPK + sp] : 0.f;
    }
    if (tid == 0) o_num[b] = (float)ndet;
}

// ---------------- launcher ----------------
extern "C" void kernel_launch(void* const* d_in, const int* in_sizes, int n_in,
                              void* d_out, int out_size)
{
    const float* p3 = (const float*)d_in[0];
    const float* p4 = (const float*)d_in[1];
    const float* p5 = (const float*)d_in[2];
    int B = in_sizes[0] / (NO * 80 * 80);
    if (B > B_MAX) B = B_MAX;

    dim3 g1((A_TOT + 255) / 256, B);
    decode_kernel<<<g1, 256>>>(p3, p4, p5);
    topk_kernel<<<B, 1024>>>();
    maskfill_kernel<<<dim3(NMS_NCHUNKS, B), 1024>>>();
    scanout_kernel<<<B, 1024>>>((float*)d_out, B);
}

// round 7
// speedup vs baseline: 2.5338x; 1.1574x over previous
#include <cuda_runtime.h>
#include <cuda_bf16.h>
#include <math.h>

// ---------------- problem constants ----------------
#define NC 80
#define REG_MAX 16
#define NO 144            // 4*REG_MAX + NC
#define A_TOT 8400        // 6400 + 1600 + 400
#define PRE_TOPK 1000
#define MAX_DET 100
#define B_MAX 32
#define NBINS 4096
#define NMS_CHUNK 64
#define NMS_WORDS 16      // ceil(1000/64)
#define NMS_NCHUNKS 16

// ---------------- scratch (device globals; no allocation allowed) ----------------
__device__ float  g_conf[B_MAX * A_TOT];
__device__ int    g_cls [B_MAX * A_TOT];
__device__ float4 g_box [B_MAX * A_TOT];
__device__ float  g_scf [B_MAX * PRE_TOPK];
__device__ float4 g_sbox[B_MAX * PRE_TOPK];
__device__ int    g_scls[B_MAX * PRE_TOPK];
__device__ unsigned long long g_mask[B_MAX * PRE_TOPK * NMS_WORDS]; // 4 MB

// ---------------- helpers ----------------
__device__ __forceinline__ unsigned f2key(float v) {
    unsigned u = __float_as_uint(v);
    return (u & 0x80000000u) ? ~u : (u | 0x80000000u);
}
__device__ __forceinline__ float key2f(unsigned k) {
    unsigned u = (k & 0x80000000u) ? (k & 0x7FFFFFFFu) : ~k;
    return __uint_as_float(u);
}
__device__ __forceinline__ int val2bin(float v) {
    float t = (v - 0.25f) * (4096.0f / 0.75f);
    int b = (int)t;
    if (b < 0) b = 0;
    if (b > NBINS - 1) b = NBINS - 1;
    return b;
}
__device__ __forceinline__ unsigned long long packkey(float v, int idx) {
    return ((unsigned long long)f2key(v) << 32) |
           (unsigned long long)(0xFFFFFFFFu - (unsigned)idx);
}

// ---------------- kernel 1: decode (bit-identical to passing rounds) ----------------
__global__ void __launch_bounds__(256) decode_kernel(const float* __restrict__ p3,
                                                     const float* __restrict__ p4,
                                                     const float* __restrict__ p5)
{
    int a = blockIdx.x * blockDim.x + threadIdx.x;
    int b = blockIdx.y;
    if (a >= A_TOT) return;

    const float* src;
    int w, local;
    float stride;
    if (a < 6400)      { src = p3; w = 80; stride = 8.f;  local = a; }
    else if (a < 8000) { src = p4; w = 40; stride = 16.f; local = a - 6400; }
    else               { src = p5; w = 20; stride = 32.f; local = a - 8000; }

    int plane = w * w;
    int y = local / w;
    int x = local - y * w;
    const float* base = src + (size_t)b * NO * plane + y * w + x;

    float best = -INFINITY;
    int bi = 0;
    #pragma unroll 4
    for (int c = 0; c < NC; ++c) {
        float v = base[(4 * REG_MAX + c) * plane];
        if (v > best) { best = v; bi = c; }
    }
    float conf = 1.0f / (1.0f + expf(-best));

    float d[4];
    #pragma unroll
    for (int k = 0; k < 4; ++k) {
        float lg[REG_MAX];
        float m = -INFINITY;
        #pragma unroll
        for (int r = 0; r < REG_MAX; ++r) {
            lg[r] = base[(k * REG_MAX + r) * plane];
            m = fmaxf(m, lg[r]);
        }
        float s = 0.f, dot = 0.f;
        #pragma unroll
        for (int r = 0; r < REG_MAX; ++r) {
            float e = expf(lg[r] - m);
            s += e;
            dot += e * (float)r;
        }
        d[k] = dot / s;
    }

    float xa = (float)x + 0.5f, ya = (float)y + 0.5f;
    float x1g = xa - d[0], y1g = ya - d[1];
    float x2g = xa + d[2], y2g = ya + d[3];
    float cx = (x1g + x2g) * 0.5f * stride;
    float cy = (y1g + y2g) * 0.5f * stride;
    float bw = (x2g - x1g) * stride;
    float bh = (y2g - y1g) * stride;

    int o = b * A_TOT + a;
    g_conf[o] = (conf > 0.25f) ? conf : -1.0f;
    g_cls[o]  = bi;
    g_box[o] = make_float4(cx - bw * 0.5f, cy - bh * 0.5f,
                           cx + bw * 0.5f, cy + bh * 0.5f);
}

// ---------------- kernel 2: top-1000 select + rank-scatter ordering ----------------
#define SM_BYTES 37120

__global__ void __launch_bounds__(1024) topk_kernel()
{
    __shared__ __align__(16) char sm[SM_BYTES];
    int*                hist  = (int*)sm;                                // [4096]
    unsigned long long* blist = (unsigned long long*)(sm + 20480);       // [1024]
    unsigned long long* cand  = (unsigned long long*)(sm + 28672);       // [1024]
    int*   ctr = (int*)(sm + 36864);
    int*   ws  = ctr + 8;

    int b    = blockIdx.x;
    int tid  = threadIdx.x;
    int lane = tid & 31;
    int wid  = tid >> 5;
    const float* conf = g_conf + b * A_TOT;

    for (int t = tid; t < NBINS; t += 1024) hist[t] = 0;
    if (tid == 0) { ctr[0] = 0; ctr[1] = 0; ctr[2] = 0; ctr[3] = 0; }
    __syncthreads();
    for (int t = tid; t < A_TOT; t += 1024)
        atomicAdd(&hist[val2bin(conf[t])], 1);
    __syncthreads();

    // suffix scan (shfl-based)
    int g = hist[4 * tid] + hist[4 * tid + 1] + hist[4 * tid + 2] + hist[4 * tid + 3];
    int s = g;
    #pragma unroll
    for (int o = 1; o < 32; o <<= 1) {
        int v = __shfl_down_sync(0xFFFFFFFFu, s, o);
        if (lane + o < 32) s += v;
    }
    if (lane == 0) ws[wid] = s;
    __syncthreads();
    if (wid == 0) {
        int v = ws[lane];
        int t2 = v;
        #pragma unroll
        for (int o = 1; o < 32; o <<= 1) {
            int u = __shfl_down_sync(0xFFFFFFFFu, t2, o);
            if (lane + o < 32) t2 += u;
        }
        ws[lane] = t2 - v;
    }
    __syncthreads();
    {
        int above = ws[wid] + (s - g);
        #pragma unroll
        for (int k = 3; k >= 0; --k) {
            int bin = 4 * tid + k;
            int cum = above + hist[bin];
            if (cum >= PRE_TOPK && above < PRE_TOPK) { ctr[2] = bin; ctr[3] = above; }
            above = cum;
        }
    }
    __syncthreads();
    int cross   = ctr[2];
    int greater = ctr[3];
    int needed  = PRE_TOPK - greater;

    for (int t = tid; t < 9216; t += 1024) {
        bool in = t < A_TOT;
        float v = in ? conf[t] : 0.f;
        int bin = in ? val2bin(v) : -1;
        bool pg = in && (bin > cross);
        unsigned mg = __ballot_sync(0xFFFFFFFFu, pg);
        if (mg) {
            int leader = __ffs(mg) - 1;
            int base = 0;
            if (lane == leader) base = atomicAdd(&ctr[0], __popc(mg));
            base = __shfl_sync(0xFFFFFFFFu, base, leader);
            if (pg) cand[base + __popc(mg & ((1u << lane) - 1u))] = packkey(v, t);
        }
        bool pe = in && (bin == cross);
        unsigned me = __ballot_sync(0xFFFFFFFFu, pe);
        if (me) {
            int leader = __ffs(me) - 1;
            int base = 0;
            if (lane == leader) base = atomicAdd(&ctr[1], __popc(me));
            base = __shfl_sync(0xFFFFFFFFu, base, leader);
            if (pe) {
                int pos = base + __popc(me & ((1u << lane) - 1u));
                if (pos < 1024) blist[pos] = packkey(v, t);
            }
        }
    }
    __syncthreads();

    int m = ctr[1];
    if (needed > 0) {
        if (m <= 1024) {
            for (int e = tid; e < m; e += 1024) {
                unsigned long long ke = blist[e];
                int rank = 0;
                for (int j = 0; j < m; ++j) rank += (blist[j] > ke) ? 1 : 0;
                if (rank < needed) cand[atomicAdd(&ctr[0], 1)] = ke;
            }
        } else {
            for (int i = tid; i < A_TOT; i += 1024) {
                float v = conf[i];
                if (val2bin(v) != cross) continue;
                unsigned long long ki = packkey(v, i);
                int rank = 0;
                for (int j = 0; j < A_TOT; ++j) {
                    float vj = conf[j];
                    if (val2bin(vj) != cross) continue;
                    rank += (packkey(vj, j) > ki) ? 1 : 0;
                }
                if (rank < needed) cand[atomicAdd(&ctr[0], 1)] = ki;
            }
        }
    }
    __syncthreads();

    // ---- rank-scatter: barrier-free ordering (keys unique) ----
    if (tid < PRE_TOPK) {
        unsigned long long ke = cand[tid];
        int rank = 0;
        for (int j = 0; j < PRE_TOPK; ++j)
            rank += (cand[j] > ke) ? 1 : 0;     // broadcast smem reads
        int si = (int)(0xFFFFFFFFu - (unsigned)ke);
        g_scf[b * PRE_TOPK + rank]  = key2f((unsigned)(ke >> 32));
        g_sbox[b * PRE_TOPK + rank] = g_box[b * A_TOT + si];
        g_scls[b * PRE_TOPK + rank] = g_cls[b * A_TOT + si];
    }
}

// ---------------- kernel 3: IoU mask fill (whole-chip parallel) ----------------
__global__ void __launch_bounds__(1024) maskfill_kernel()
{
    __shared__ float bx1[PRE_TOPK], by1[PRE_TOPK], bx2[PRE_TOPK], by2[PRE_TOPK];
    int c  = blockIdx.x;
    int b  = blockIdx.y;
    int tid = threadIdx.x;

    for (int t = tid; t < PRE_TOPK; t += 1024) {
        float4 bb = g_sbox[b * PRE_TOPK + t];
        bx1[t] = bb.x; by1[t] = bb.y; bx2[t] = bb.z; by2[t] = bb.w;
    }
    __syncthreads();

    int i  = c * NMS_CHUNK + (tid >> 4);
    int wd = tid & 15;
    if (i >= PRE_TOPK) return;

    float ax1 = bx1[i], ay1 = by1[i], ax2 = bx2[i], ay2 = by2[i];
    float areaA = (ax2 - ax1) * (ay2 - ay1);
    unsigned long long mword = 0ull;
    int j0 = wd * 64;
    int jend = min(j0 + 64, PRE_TOPK);
    for (int j = max(j0, i + 1); j < jend; ++j) {
        float ix1 = fmaxf(ax1, bx1[j]);
        float iy1 = fmaxf(ay1, by1[j]);
        float ix2 = fminf(ax2, bx2[j]);
        float iy2 = fminf(ay2, by2[j]);
        float iw = fmaxf(ix2 - ix1, 0.f);
        float ih = fmaxf(iy2 - iy1, 0.f);
        float inter = iw * ih;
        float areaB = (bx2[j] - bx1[j]) * (by2[j] - by1[j]);
        float iou = inter / (areaA + areaB - inter + 1e-7f);
        if (iou > 0.45f) mword |= (1ull << (j - j0));
    }
    g_mask[(b * PRE_TOPK + i) * NMS_WORDS + wd] = mword;
}

// ---------------- kernel 4: register-resident greedy scan + output ----------------
// dynamic smem layout
#define SCAN_MASK_OFF   0                              // u64[16000] = 128000 B
#define SCAN_CF_OFF     128000                         // float[1000]
#define SCAN_CFPOS_OFF  132000                         // u64[16]
#define SCAN_KEEP_OFF   132128                         // u64[16]
#define SCAN_DET_OFF    132256                         // int[100]
#define SCAN_CNT_OFF    132656                         // int[20]
#define SCAN_SM_BYTES   132800

__global__ void __launch_bounds__(256) scanout_kernel(float* __restrict__ out, int B)
{
    extern __shared__ __align__(16) char dsm[];
    unsigned long long* smask  = (unsigned long long*)(dsm + SCAN_MASK_OFF);
    float*              cf     = (float*)(dsm + SCAN_CF_OFF);
    unsigned long long* cfpos  = (unsigned long long*)(dsm + SCAN_CFPOS_OFF);
    unsigned long long* keepm  = (unsigned long long*)(dsm + SCAN_KEEP_OFF);
    int*                detsrc = (int*)(dsm + SCAN_DET_OFF);
    int*                cnt    = (int*)(dsm + SCAN_CNT_OFF);  // [0..15] word prefix, [16] total

    int b   = blockIdx.x;
    int tid = threadIdx.x;

    // stage entire mask block + scores into smem (coalesced, L2-resident)
    const unsigned long long* gm = g_mask + (size_t)b * PRE_TOPK * NMS_WORDS;
    for (int t = tid; t < PRE_TOPK * NMS_WORDS; t += 256) smask[t] = gm[t];
    for (int t = tid; t < PRE_TOPK; t += 256) cf[t] = g_scf[b * PRE_TOPK + t];
    __syncthreads();

    // conf>0 bitmask: threads 0..15 each build one 64-bit word
    if (tid < NMS_WORDS) {
        unsigned long long w = 0ull;
        int i0 = tid * 64;
        int nb = min(64, PRE_TOPK - i0);
        for (int k = 0; k < nb; ++k)
            if (cf[i0 + k] > 0.f) w |= (1ull << k);
        cfpos[tid] = w;
    }
    __syncthreads();

    // single-thread greedy scan: rem[16] fully register-resident
    if (tid == 0) {
        unsigned long long rem[NMS_WORDS];
        #pragma unroll
        for (int k = 0; k < NMS_WORDS; ++k) rem[k] = 0ull;

        #pragma unroll
        for (int c = 0; c < NMS_WORDS; ++c) {
            unsigned long long cfp = cfpos[c];
            unsigned long long km  = 0ull;
            for (int bit = 0; bit < 64; ++bit) {
                unsigned long long bm = 1ull << bit;
                if ((cfp & bm) && !(rem[c] & bm)) {
                    km |= bm;
                    const unsigned long long* mrow = smask + (c * 64 + bit) * NMS_WORDS;
                    #pragma unroll
                    for (int k = 0; k < NMS_WORDS; ++k) rem[k] |= mrow[k];
                }
            }
            keepm[c] = km;
        }
    }
    __syncthreads();

    // extraction: popc + prefix over 16 words, then walk set bits (index-asc order)
    if (tid < NMS_WORDS) {
        int c = __popcll(keepm[tid]);
        int p = c;
        #pragma unroll
        for (int o = 1; o < NMS_WORDS; o <<= 1) {
            int u = __shfl_up_sync(0x0000FFFFu, p, o, 16);
            if ((tid & 15) >= o) p += u;
        }
        cnt[tid] = p - c;                       // exclusive prefix
        if (tid == NMS_WORDS - 1) cnt[16] = p;  // total kept
    }
    __syncthreads();
    if (tid < NMS_WORDS) {
        unsigned long long w = keepm[tid];
        int p = cnt[tid];
        while (w) {
            int bit = __ffsll((long long)w) - 1;
            w &= w - 1;
            if (p < MAX_DET) detsrc[p] = tid * 64 + bit;
            ++p;
        }
    }
    __syncthreads();
    int ndet = min(cnt[16], MAX_DET);

    // output: [num_dets (B)] [boxes (B*100*4)] [scores (B*100)] [classes (B*100)]
    float* o_num = out;
    float* o_box = out + B;
    float* o_sc  = out + B + B * MAX_DET * 4;
    float* o_cl  = out + B + B * MAX_DET * 5;

    if (tid < MAX_DET) {
        bool valid = tid < ndet;
        int sp = valid ? detsrc[tid] : 0;
        o_sc[b * MAX_DET + tid] = valid ? cf[sp] : 0.f;
        float4 bb = valid ? g_sbox[b * PRE_TOPK + sp]
                          : make_float4(0.f, 0.f, 0.f, 0.f);
        ((float4*)o_box)[b * MAX_DET + tid] = bb;
        o_cl[b * MAX_DET + tid] = valid ? (float)g_scls[b * PRE_TOPK + sp] : 0.f;
    }
    if (tid == 0) o_num[b] = (float)ndet;
}

// ---------------- launcher ----------------
extern "C" void kernel_launch(void* const* d_in, const int* in_sizes, int n_in,
                              void* d_out, int out_size)
{
    const float* p3 = (const float*)d_in[0];
    const float* p4 = (const float*)d_in[1];
    const float* p5 = (const float*)d_in[2];
    int B = in_sizes[0] / (NO * 80 * 80);
    if (B > B_MAX) B = B_MAX;

    dim3 g1((A_TOT + 255) / 256, B);
    decode_kernel<<<g1, 256>>>(p3, p4, p5);
    topk_kernel<<<B, 1024>>>();
    maskfill_kernel<<<dim3(NMS_NCHUNKS, B), 1024>>>();

    cudaFuncSetAttribute(scanout_kernel,
                         cudaFuncAttributeMaxDynamicSharedMemorySize,
                         SCAN_SM_BYTES);
    scanout_kernel<<<B, 256, SCAN_SM_BYTES>>>((float*)d_out, B);
}

// round 8
// speedup vs baseline: 2.6560x; 1.0482x over previous
#include <cuda_runtime.h>
#include <cuda_bf16.h>
#include <math.h>

// ---------------- problem constants ----------------
#define NC 80
#define REG_MAX 16
#define NO 144            // 4*REG_MAX + NC
#define A_TOT 8400        // 6400 + 1600 + 400
#define PRE_TOPK 1000
#define MAX_DET 100
#define B_MAX 32
#define NBINS 4096
#define NMS_CHUNK 64
#define NMS_WORDS 16      // ceil(1000/64)
#define NMS_NCHUNKS 16

// ---------------- scratch (device globals; no allocation allowed) ----------------
__device__ float  g_conf[B_MAX * A_TOT];
__device__ int    g_cls [B_MAX * A_TOT];
__device__ float4 g_box [B_MAX * A_TOT];
__device__ float  g_scf [B_MAX * PRE_TOPK];
__device__ float4 g_sbox[B_MAX * PRE_TOPK];
__device__ int    g_scls[B_MAX * PRE_TOPK];
__device__ unsigned long long g_mask[B_MAX * PRE_TOPK * NMS_WORDS]; // 4 MB

// ---------------- helpers ----------------
__device__ __forceinline__ unsigned f2key(float v) {
    unsigned u = __float_as_uint(v);
    return (u & 0x80000000u) ? ~u : (u | 0x80000000u);
}
__device__ __forceinline__ float key2f(unsigned k) {
    unsigned u = (k & 0x80000000u) ? (k & 0x7FFFFFFFu) : ~k;
    return __uint_as_float(u);
}
__device__ __forceinline__ int val2bin(float v) {
    float t = (v - 0.25f) * (4096.0f / 0.75f);
    int b = (int)t;
    if (b < 0) b = 0;
    if (b > NBINS - 1) b = NBINS - 1;
    return b;
}
__device__ __forceinline__ unsigned long long packkey(float v, int idx) {
    return ((unsigned long long)f2key(v) << 32) |
           (unsigned long long)(0xFFFFFFFFu - (unsigned)idx);
}

// ---------------- kernel 1: decode (bit-identical to passing rounds) ----------------
__global__ void __launch_bounds__(256) decode_kernel(const float* __restrict__ p3,
                                                     const float* __restrict__ p4,
                                                     const float* __restrict__ p5)
{
    int a = blockIdx.x * blockDim.x + threadIdx.x;
    int b = blockIdx.y;
    if (a >= A_TOT) return;

    const float* src;
    int w, local;
    float stride;
    if (a < 6400)      { src = p3; w = 80; stride = 8.f;  local = a; }
    else if (a < 8000) { src = p4; w = 40; stride = 16.f; local = a - 6400; }
    else               { src = p5; w = 20; stride = 32.f; local = a - 8000; }

    int plane = w * w;
    int y = local / w;
    int x = local - y * w;
    const float* base = src + (size_t)b * NO * plane + y * w + x;

    float best = -INFINITY;
    int bi = 0;
    #pragma unroll 4
    for (int c = 0; c < NC; ++c) {
        float v = base[(4 * REG_MAX + c) * plane];
        if (v > best) { best = v; bi = c; }
    }
    float conf = 1.0f / (1.0f + expf(-best));

    float d[4];
    #pragma unroll
    for (int k = 0; k < 4; ++k) {
        float lg[REG_MAX];
        float m = -INFINITY;
        #pragma unroll
        for (int r = 0; r < REG_MAX; ++r) {
            lg[r] = base[(k * REG_MAX + r) * plane];
            m = fmaxf(m, lg[r]);
        }
        float s = 0.f, dot = 0.f;
        #pragma unroll
        for (int r = 0; r < REG_MAX; ++r) {
            float e = expf(lg[r] - m);
            s += e;
            dot += e * (float)r;
        }
        d[k] = dot / s;
    }

    float xa = (float)x + 0.5f, ya = (float)y + 0.5f;
    float x1g = xa - d[0], y1g = ya - d[1];
    float x2g = xa + d[2], y2g = ya + d[3];
    float cx = (x1g + x2g) * 0.5f * stride;
    float cy = (y1g + y2g) * 0.5f * stride;
    float bw = (x2g - x1g) * stride;
    float bh = (y2g - y1g) * stride;

    int o = b * A_TOT + a;
    g_conf[o] = (conf > 0.25f) ? conf : -1.0f;
    g_cls[o]  = bi;
    g_box[o] = make_float4(cx - bw * 0.5f, cy - bh * 0.5f,
                           cx + bw * 0.5f, cy + bh * 0.5f);
}

// ---------------- kernel 2: top-1000 select + rank-scatter ordering ----------------
#define SM_BYTES 37120

__global__ void __launch_bounds__(1024) topk_kernel()
{
    __shared__ __align__(16) char sm[SM_BYTES];
    int*                hist  = (int*)sm;                                // [4096]
    unsigned long long* blist = (unsigned long long*)(sm + 20480);       // [1024]
    unsigned long long* cand  = (unsigned long long*)(sm + 28672);       // [1024]
    int*   ctr = (int*)(sm + 36864);
    int*   ws  = ctr + 8;

    int b    = blockIdx.x;
    int tid  = threadIdx.x;
    int lane = tid & 31;
    int wid  = tid >> 5;
    const float* conf = g_conf + b * A_TOT;

    for (int t = tid; t < NBINS; t += 1024) hist[t] = 0;
    if (tid == 0) { ctr[0] = 0; ctr[1] = 0; ctr[2] = 0; ctr[3] = 0; }
    __syncthreads();
    for (int t = tid; t < A_TOT; t += 1024)
        atomicAdd(&hist[val2bin(conf[t])], 1);
    __syncthreads();

    // suffix scan (shfl-based)
    int g = hist[4 * tid] + hist[4 * tid + 1] + hist[4 * tid + 2] + hist[4 * tid + 3];
    int s = g;
    #pragma unroll
    for (int o = 1; o < 32; o <<= 1) {
        int v = __shfl_down_sync(0xFFFFFFFFu, s, o);
        if (lane + o < 32) s += v;
    }
    if (lane == 0) ws[wid] = s;
    __syncthreads();
    if (wid == 0) {
        int v = ws[lane];
        int t2 = v;
        #pragma unroll
        for (int o = 1; o < 32; o <<= 1) {
            int u = __shfl_down_sync(0xFFFFFFFFu, t2, o);
            if (lane + o < 32) t2 += u;
        }
        ws[lane] = t2 - v;
    }
    __syncthreads();
    {
        int above = ws[wid] + (s - g);
        #pragma unroll
        for (int k = 3; k >= 0; --k) {
            int bin = 4 * tid + k;
            int cum = above + hist[bin];
            if (cum >= PRE_TOPK && above < PRE_TOPK) { ctr[2] = bin; ctr[3] = above; }
            above = cum;
        }
    }
    __syncthreads();
    int cross   = ctr[2];
    int greater = ctr[3];
    int needed  = PRE_TOPK - greater;

    for (int t = tid; t < 9216; t += 1024) {
        bool in = t < A_TOT;
        float v = in ? conf[t] : 0.f;
        int bin = in ? val2bin(v) : -1;
        bool pg = in && (bin > cross);
        unsigned mg = __ballot_sync(0xFFFFFFFFu, pg);
        if (mg) {
            int leader = __ffs(mg) - 1;
            int base = 0;
            if (lane == leader) base = atomicAdd(&ctr[0], __popc(mg));
            base = __shfl_sync(0xFFFFFFFFu, base, leader);
            if (pg) cand[base + __popc(mg & ((1u << lane) - 1u))] = packkey(v, t);
        }
        bool pe = in && (bin == cross);
        unsigned me = __ballot_sync(0xFFFFFFFFu, pe);
        if (me) {
            int leader = __ffs(me) - 1;
            int base = 0;
            if (lane == leader) base = atomicAdd(&ctr[1], __popc(me));
            base = __shfl_sync(0xFFFFFFFFu, base, leader);
            if (pe) {
                int pos = base + __popc(me & ((1u << lane) - 1u));
                if (pos < 1024) blist[pos] = packkey(v, t);
            }
        }
    }
    __syncthreads();

    int m = ctr[1];
    if (needed > 0) {
        if (m <= 1024) {
            for (int e = tid; e < m; e += 1024) {
                unsigned long long ke = blist[e];
                int rank = 0;
                for (int j = 0; j < m; ++j) rank += (blist[j] > ke) ? 1 : 0;
                if (rank < needed) cand[atomicAdd(&ctr[0], 1)] = ke;
            }
        } else {
            for (int i = tid; i < A_TOT; i += 1024) {
                float v = conf[i];
                if (val2bin(v) != cross) continue;
                unsigned long long ki = packkey(v, i);
                int rank = 0;
                for (int j = 0; j < A_TOT; ++j) {
                    float vj = conf[j];
                    if (val2bin(vj) != cross) continue;
                    rank += (packkey(vj, j) > ki) ? 1 : 0;
                }
                if (rank < needed) cand[atomicAdd(&ctr[0], 1)] = ki;
            }
        }
    }
    __syncthreads();

    // rank-scatter: barrier-free ordering (keys unique)
    if (tid < PRE_TOPK) {
        unsigned long long ke = cand[tid];
        int rank = 0;
        for (int j = 0; j < PRE_TOPK; ++j)
            rank += (cand[j] > ke) ? 1 : 0;
        int si = (int)(0xFFFFFFFFu - (unsigned)ke);
        g_scf[b * PRE_TOPK + rank]  = key2f((unsigned)(ke >> 32));
        g_sbox[b * PRE_TOPK + rank] = g_box[b * A_TOT + si];
        g_scls[b * PRE_TOPK + rank] = g_cls[b * A_TOT + si];
    }
}

// ---------------- kernel 3: IoU mask fill (band test, divide only near boundary) ----------------
__global__ void __launch_bounds__(1024) maskfill_kernel()
{
    __shared__ float bx1[PRE_TOPK], by1[PRE_TOPK], bx2[PRE_TOPK], by2[PRE_TOPK];
    int c  = blockIdx.x;
    int b  = blockIdx.y;
    int tid = threadIdx.x;

    for (int t = tid; t < PRE_TOPK; t += 1024) {
        float4 bb = g_sbox[b * PRE_TOPK + t];
        bx1[t] = bb.x; by1[t] = bb.y; bx2[t] = bb.z; by2[t] = bb.w;
    }
    __syncthreads();

    int i  = c * NMS_CHUNK + (tid >> 4);
    int wd = tid & 15;
    if (i >= PRE_TOPK) return;

    float ax1 = bx1[i], ay1 = by1[i], ax2 = bx2[i], ay2 = by2[i];
    float areaA = (ax2 - ax1) * (ay2 - ay1);
    unsigned long long mword = 0ull;
    int j0 = wd * 64;
    int jend = min(j0 + 64, PRE_TOPK);
    for (int j = max(j0, i + 1); j < jend; ++j) {
        float ix1 = fmaxf(ax1, bx1[j]);
        float iy1 = fmaxf(ay1, by1[j]);
        float ix2 = fminf(ax2, bx2[j]);
        float iy2 = fminf(ay2, by2[j]);
        float iw = fmaxf(ix2 - ix1, 0.f);
        float ih = fmaxf(iy2 - iy1, 0.f);
        float inter = iw * ih;
        float areaB = (bx2[j] - bx1[j]) * (by2[j] - by1[j]);
        float u = areaA + areaB - inter + 1e-7f;
        // band test: decision provably identical to (inter/u > 0.45f) outside
        // the +-1e-3*u band (fp32 rounding ~1e-7 rel << 1e-3); exact divide inside.
        float dd  = inter - 0.45f * u;
        float bnd = 1e-3f * u;
        bool sup;
        if (dd > bnd)       sup = true;
        else if (dd < -bnd) sup = false;
        else                sup = (inter / u) > 0.45f;   // original expression
        if (sup) mword |= (1ull << (j - j0));
    }
    g_mask[(b * PRE_TOPK + i) * NMS_WORDS + wd] = mword;
}

// ---------------- kernel 4: kept-only greedy scan + output ----------------
#define SCAN_MASK_OFF   0                              // u64[16000] = 128000 B
#define SCAN_CF_OFF     128000                         // float[1000]
#define SCAN_CFPOS_OFF  132000                         // u64[16]
#define SCAN_KEEP_OFF   132128                         // u64[16]
#define SCAN_DET_OFF    132256                         // int[100]
#define SCAN_CNT_OFF    132656                         // int[20]
#define SCAN_SM_BYTES   132800

__global__ void __launch_bounds__(256) scanout_kernel(float* __restrict__ out, int B)
{
    extern __shared__ __align__(16) char dsm[];
    unsigned long long* smask  = (unsigned long long*)(dsm + SCAN_MASK_OFF);
    float*              cf     = (float*)(dsm + SCAN_CF_OFF);
    unsigned long long* cfpos  = (unsigned long long*)(dsm + SCAN_CFPOS_OFF);
    unsigned long long* keepm  = (unsigned long long*)(dsm + SCAN_KEEP_OFF);
    int*                detsrc = (int*)(dsm + SCAN_DET_OFF);
    int*                cnt    = (int*)(dsm + SCAN_CNT_OFF);

    int b   = blockIdx.x;
    int tid = threadIdx.x;

    const unsigned long long* gm = g_mask + (size_t)b * PRE_TOPK * NMS_WORDS;
    for (int t = tid; t < PRE_TOPK * NMS_WORDS; t += 256) smask[t] = gm[t];
    for (int t = tid; t < PRE_TOPK; t += 256) cf[t] = g_scf[b * PRE_TOPK + t];
    __syncthreads();

    if (tid < NMS_WORDS) {
        unsigned long long w = 0ull;
        int i0 = tid * 64;
        int nb = min(64, PRE_TOPK - i0);
        for (int k = 0; k < nb; ++k)
            if (cf[i0 + k] > 0.f) w |= (1ull << k);
        cfpos[tid] = w;
    }
    __syncthreads();

    // single-thread greedy scan, kept-only iterations
    if (tid == 0) {
        unsigned long long rem[NMS_WORDS];
        #pragma unroll
        for (int k = 0; k < NMS_WORDS; ++k) rem[k] = 0ull;

        #pragma unroll
        for (int c = 0; c < NMS_WORDS; ++c) {
            unsigned long long w  = cfpos[c] & ~rem[c];  // surviving candidates
            unsigned long long km = 0ull;
            while (w) {
                int bit = __ffsll((long long)w) - 1;
                unsigned long long bm = 1ull << bit;
                km |= bm;
                const unsigned long long* mrow = smask + (c * 64 + bit) * NMS_WORDS;
                unsigned long long rc = mrow[c];         // critical-path word
                #pragma unroll
                for (int k = 0; k < NMS_WORDS; ++k) rem[k] |= mrow[k];
                w &= ~(bm | rc);                         // clear self + newly suppressed
            }
            keepm[c] = km;
        }
    }
    __syncthreads();

    // extraction: popc + prefix over 16 words, then walk set bits (index-asc)
    if (tid < NMS_WORDS) {
        int c = __popcll(keepm[tid]);
        int p = c;
        #pragma unroll
        for (int o = 1; o < NMS_WORDS; o <<= 1) {
            int u = __shfl_up_sync(0x0000FFFFu, p, o, 16);
            if ((tid & 15) >= o) p += u;
        }
        cnt[tid] = p - c;
        if (tid == NMS_WORDS - 1) cnt[16] = p;
    }
    __syncthreads();
    if (tid < NMS_WORDS) {
        unsigned long long w = keepm[tid];
        int p = cnt[tid];
        while (w) {
            int bit = __ffsll((long long)w) - 1;
            w &= w - 1;
            if (p < MAX_DET) detsrc[p] = tid * 64 + bit;
            ++p;
        }
    }
    __syncthreads();
    int ndet = min(cnt[16], MAX_DET);

    float* o_num = out;
    float* o_box = out + B;
    float* o_sc  = out + B + B * MAX_DET * 4;
    float* o_cl  = out + B + B * MAX_DET * 5;

    if (tid < MAX_DET) {
        bool valid = tid < ndet;
        int sp = valid ? detsrc[tid] : 0;
        o_sc[b * MAX_DET + tid] = valid ? cf[sp] : 0.f;
        float4 bb = valid ? g_sbox[b * PRE_TOPK + sp]
                          : make_float4(0.f, 0.f, 0.f, 0.f);
        ((float4*)o_box)[b * MAX_DET + tid] = bb;
        o_cl[b * MAX_DET + tid] = valid ? (float)g_scls[b * PRE_TOPK + sp] : 0.f;
    }
    if (tid == 0) o_num[b] = (float)ndet;
}

// ---------------- launcher ----------------
extern "C" void kernel_launch(void* const* d_in, const int* in_sizes, int n_in,
                              void* d_out, int out_size)
{
    const float* p3 = (const float*)d_in[0];
    const float* p4 = (const float*)d_in[1];
    const float* p5 = (const float*)d_in[2];
    int B = in_sizes[0] / (NO * 80 * 80);
    if (B > B_MAX) B = B_MAX;

    dim3 g1((A_TOT + 255) / 256, B);
    decode_kernel<<<g1, 256>>>(p3, p4, p5);
    topk_kernel<<<B, 1024>>>();
    maskfill_kernel<<<dim3(NMS_NCHUNKS, B), 1024>>>();

    cudaFuncSetAttribute(scanout_kernel,
                         cudaFuncAttributeMaxDynamicSharedMemorySize,
                         SCAN_SM_BYTES);
    scanout_kernel<<<B, 256, SCAN_SM_BYTES>>>((float*)d_out, B);
}

// round 9
// speedup vs baseline: 5.1917x; 1.9547x over previous
#include <cuda_runtime.h>
#include <cuda_bf16.h>
#include <math.h>

// ---------------- problem constants ----------------
#define NC 80
#define REG_MAX 16
#define NO 144            // 4*REG_MAX + NC
#define A_TOT 8400        // 6400 + 1600 + 400
#define PRE_TOPK 1000
#define MAX_DET 100
#define B_MAX 32
#define NBINS 4096

// ---------------- scratch (device globals; no allocation allowed) ----------------
__device__ float  g_conf[B_MAX * A_TOT];
__device__ int    g_cls [B_MAX * A_TOT];
__device__ float4 g_box [B_MAX * A_TOT];

// ---------------- helpers ----------------
__device__ __forceinline__ unsigned f2key(float v) {
    unsigned u = __float_as_uint(v);
    return (u & 0x80000000u) ? ~u : (u | 0x80000000u);
}
__device__ __forceinline__ float key2f(unsigned k) {
    unsigned u = (k & 0x80000000u) ? (k & 0x7FFFFFFFu) : ~k;
    return __uint_as_float(u);
}
__device__ __forceinline__ int val2bin(float v) {
    float t = (v - 0.25f) * (4096.0f / 0.75f);
    int b = (int)t;
    if (b < 0) b = 0;
    if (b > NBINS - 1) b = NBINS - 1;
    return b;
}
__device__ __forceinline__ unsigned long long packkey(float v, int idx) {
    return ((unsigned long long)f2key(v) << 32) |
           (unsigned long long)(0xFFFFFFFFu - (unsigned)idx);
}

// ---------------- kernel 1: decode (bit-identical to passing rounds) ----------------
__global__ void __launch_bounds__(256) decode_kernel(const float* __restrict__ p3,
                                                     const float* __restrict__ p4,
                                                     const float* __restrict__ p5)
{
    int a = blockIdx.x * blockDim.x + threadIdx.x;
    int b = blockIdx.y;
    if (a >= A_TOT) return;

    const float* src;
    int w, local;
    float stride;
    if (a < 6400)      { src = p3; w = 80; stride = 8.f;  local = a; }
    else if (a < 8000) { src = p4; w = 40; stride = 16.f; local = a - 6400; }
    else               { src = p5; w = 20; stride = 32.f; local = a - 8000; }

    int plane = w * w;
    int y = local / w;
    int x = local - y * w;
    const float* base = src + (size_t)b * NO * plane + y * w + x;

    float best = -INFINITY;
    int bi = 0;
    #pragma unroll 4
    for (int c = 0; c < NC; ++c) {
        float v = base[(4 * REG_MAX + c) * plane];
        if (v > best) { best = v; bi = c; }
    }
    float conf = 1.0f / (1.0f + expf(-best));

    float d[4];
    #pragma unroll
    for (int k = 0; k < 4; ++k) {
        float lg[REG_MAX];
        float m = -INFINITY;
        #pragma unroll
        for (int r = 0; r < REG_MAX; ++r) {
            lg[r] = base[(k * REG_MAX + r) * plane];
            m = fmaxf(m, lg[r]);
        }
        float s = 0.f, dot = 0.f;
        #pragma unroll
        for (int r = 0; r < REG_MAX; ++r) {
            float e = expf(lg[r] - m);
            s += e;
            dot += e * (float)r;
        }
        d[k] = dot / s;
    }

    float xa = (float)x + 0.5f, ya = (float)y + 0.5f;
    float x1g = xa - d[0], y1g = ya - d[1];
    float x2g = xa + d[2], y2g = ya + d[3];
    float cx = (x1g + x2g) * 0.5f * stride;
    float cy = (y1g + y2g) * 0.5f * stride;
    float bw = (x2g - x1g) * stride;
    float bh = (y2g - y1g) * stride;

    int o = b * A_TOT + a;
    g_conf[o] = (conf > 0.25f) ? conf : -1.0f;
    g_cls[o]  = bi;
    g_box[o] = make_float4(cx - bw * 0.5f, cy - bh * 0.5f,
                           cx + bw * 0.5f, cy + bh * 0.5f);
}

// ---------------- kernel 2: fused topk + frontier NMS + output ----------------
// smem layout (37120 B), phase-aliased:
//   phase 1 (select):  hist@0 [4096 int], blist@20480 [1024 u64], cand@28672 [1024 u64]
//   phase 2 (NMS):     bx1@0, by1@4096, bx2@8192, by2@12288, cf@16384, scls@20480
//                      aw@24576 [32 u32], dets@24704 [100 int]
//   always:            ctr@36864 [8 int], ws@36896 [32 int]
#define SM_BYTES 37120

__global__ void __launch_bounds__(1024) fused_post_kernel(float* __restrict__ out, int B)
{
    __shared__ __align__(16) char sm[SM_BYTES];
    int*                hist  = (int*)sm;
    unsigned long long* blist = (unsigned long long*)(sm + 20480);
    unsigned long long* cand  = (unsigned long long*)(sm + 28672);
    float* bx1 = (float*)(sm + 0);
    float* by1 = (float*)(sm + 4096);
    float* bx2 = (float*)(sm + 8192);
    float* by2 = (float*)(sm + 12288);
    float* cf  = (float*)(sm + 16384);
    int*   scls = (int*)(sm + 20480);
    unsigned* aw  = (unsigned*)(sm + 24576);
    int*   dets  = (int*)(sm + 24704);
    int*   ctr = (int*)(sm + 36864);
    int*   ws  = ctr + 8;

    int b    = blockIdx.x;
    int tid  = threadIdx.x;
    int lane = tid & 31;
    int wid  = tid >> 5;
    const float* conf = g_conf + b * A_TOT;

    // ---------- phase 1a: histogram ----------
    for (int t = tid; t < NBINS; t += 1024) hist[t] = 0;
    if (tid == 0) { ctr[0] = 0; ctr[1] = 0; ctr[2] = 0; ctr[3] = 0; ctr[5] = 0; }
    __syncthreads();
    for (int t = tid; t < A_TOT; t += 1024)
        atomicAdd(&hist[val2bin(conf[t])], 1);
    __syncthreads();

    // ---------- phase 1b: suffix scan ----------
    int g = hist[4 * tid] + hist[4 * tid + 1] + hist[4 * tid + 2] + hist[4 * tid + 3];
    int s = g;
    #pragma unroll
    for (int o = 1; o < 32; o <<= 1) {
        int v = __shfl_down_sync(0xFFFFFFFFu, s, o);
        if (lane + o < 32) s += v;
    }
    if (lane == 0) ws[wid] = s;
    __syncthreads();
    if (wid == 0) {
        int v = ws[lane];
        int t2 = v;
        #pragma unroll
        for (int o = 1; o < 32; o <<= 1) {
            int u = __shfl_down_sync(0xFFFFFFFFu, t2, o);
            if (lane + o < 32) t2 += u;
        }
        ws[lane] = t2 - v;
    }
    __syncthreads();
    {
        int above = ws[wid] + (s - g);
        #pragma unroll
        for (int k = 3; k >= 0; --k) {
            int bin = 4 * tid + k;
            int cum = above + hist[bin];
            if (cum >= PRE_TOPK && above < PRE_TOPK) { ctr[2] = bin; ctr[3] = above; }
            above = cum;
        }
    }
    __syncthreads();
    int cross   = ctr[2];
    int greater = ctr[3];
    int needed  = PRE_TOPK - greater;

    // ---------- phase 1c: compaction ----------
    for (int t = tid; t < 9216; t += 1024) {
        bool in = t < A_TOT;
        float v = in ? conf[t] : 0.f;
        int bin = in ? val2bin(v) : -1;
        bool pg = in && (bin > cross);
        unsigned mg = __ballot_sync(0xFFFFFFFFu, pg);
        if (mg) {
            int leader = __ffs(mg) - 1;
            int base = 0;
            if (lane == leader) base = atomicAdd(&ctr[0], __popc(mg));
            base = __shfl_sync(0xFFFFFFFFu, base, leader);
            if (pg) cand[base + __popc(mg & ((1u << lane) - 1u))] = packkey(v, t);
        }
        bool pe = in && (bin == cross);
        unsigned me = __ballot_sync(0xFFFFFFFFu, pe);
        if (me) {
            int leader = __ffs(me) - 1;
            int base = 0;
            if (lane == leader) base = atomicAdd(&ctr[1], __popc(me));
            base = __shfl_sync(0xFFFFFFFFu, base, leader);
            if (pe) {
                int pos = base + __popc(me & ((1u << lane) - 1u));
                if (pos < 1024) blist[pos] = packkey(v, t);
            }
        }
    }
    __syncthreads();

    // ---------- phase 1d: boundary rank selection ----------
    int m = ctr[1];
    if (needed > 0) {
        if (m <= 1024) {
            for (int e = tid; e < m; e += 1024) {
                unsigned long long ke = blist[e];
                int rank = 0;
                for (int j = 0; j < m; ++j) rank += (blist[j] > ke) ? 1 : 0;
                if (rank < needed) cand[atomicAdd(&ctr[0], 1)] = ke;
            }
        } else {
            for (int i = tid; i < A_TOT; i += 1024) {
                float v = conf[i];
                if (val2bin(v) != cross) continue;
                unsigned long long ki = packkey(v, i);
                int rank = 0;
                for (int j = 0; j < A_TOT; ++j) {
                    float vj = conf[j];
                    if (val2bin(vj) != cross) continue;
                    rank += (packkey(vj, j) > ki) ? 1 : 0;
                }
                if (rank < needed) cand[atomicAdd(&ctr[0], 1)] = ki;
            }
        }
    }
    __syncthreads();
    if (tid >= PRE_TOPK) cand[tid] = 0ull;
    __syncthreads();

    // ---------- phase 1e: rank-scatter into smem (hist/blist dead) ----------
    if (tid < PRE_TOPK) {
        unsigned long long ke = cand[tid];
        int rank = 0;
        for (int j = 0; j < PRE_TOPK; ++j)
            rank += (cand[j] > ke) ? 1 : 0;     // broadcast smem reads
        int si = (int)(0xFFFFFFFFu - (unsigned)ke);
        float4 bb = g_box[b * A_TOT + si];
        cf[rank]  = key2f((unsigned)(ke >> 32));
        bx1[rank] = bb.x; by1[rank] = bb.y;
        bx2[rank] = bb.z; by2[rank] = bb.w;
        scls[rank] = g_cls[b * A_TOT + si];
    }
    __syncthreads();

    // ---------- phase 2: frontier NMS (<=100 steps, exact IoU) ----------
    float x1 = 0.f, y1 = 0.f, x2 = 0.f, y2 = 0.f, mycf = -1.f;
    if (tid < PRE_TOPK) {
        x1 = bx1[tid]; y1 = by1[tid]; x2 = bx2[tid]; y2 = by2[tid];
        mycf = cf[tid];
    }
    bool alive = (tid < PRE_TOPK) && (mycf > 0.f);
    float areaB = (x2 - x1) * (y2 - y1);

    {
        unsigned bal = __ballot_sync(0xFFFFFFFFu, alive);
        if (lane == 0) aw[wid] = bal;
    }
    __syncthreads();

    for (;;) {
        if (wid == 0) {
            unsigned w = aw[lane];
            unsigned nz = __ballot_sync(0xFFFFFFFFu, w != 0);
            int cur = -1;
            if (nz) {
                int fw = __ffs(nz) - 1;
                unsigned word = __shfl_sync(0xFFFFFFFFu, w, fw);
                cur = fw * 32 + __ffs(word) - 1;
            }
            if (lane == 0) {
                ctr[6] = cur;
                if (cur >= 0) { dets[ctr[5]] = cur; ctr[5] = ctr[5] + 1; }
            }
        }
        __syncthreads();
        int cur = ctr[6];
        int nd  = ctr[5];
        if (cur < 0) break;

        float ax1 = bx1[cur], ay1 = by1[cur], ax2 = bx2[cur], ay2 = by2[cur];
        if (alive) {
            if (tid == cur) alive = false;
            else if (tid > cur) {
                float areaA = (ax2 - ax1) * (ay2 - ay1);
                float ix1 = fmaxf(ax1, x1);
                float iy1 = fmaxf(ay1, y1);
                float ix2 = fminf(ax2, x2);
                float iy2 = fminf(ay2, y2);
                float iw = fmaxf(ix2 - ix1, 0.f);
                float ih = fmaxf(iy2 - iy1, 0.f);
                float inter = iw * ih;
                float iou = inter / (areaA + areaB - inter + 1e-7f);
                if (iou > 0.45f) alive = false;
            }
        }
        unsigned nb = __ballot_sync(0xFFFFFFFFu, alive);
        if (lane == 0) aw[wid] = nb;
        if (nd >= MAX_DET) break;
        __syncthreads();
    }
    __syncthreads();

    int ndet = ctr[5];
    if (ndet > MAX_DET) ndet = MAX_DET;

    // ---------- phase 3: output ----------
    // layout: [num_dets (B)] [boxes (B*100*4)] [scores (B*100)] [classes (B*100)]
    float* o_num = out;
    float* o_box = out + B;
    float* o_sc  = out + B + B * MAX_DET * 4;
    float* o_cl  = out + B + B * MAX_DET * 5;

    if (tid < MAX_DET) {
        bool valid = tid < ndet;
        int sp = valid ? dets[tid] : 0;
        o_sc[b * MAX_DET + tid] = valid ? cf[sp] : 0.f;
        float4 bb = valid ? make_float4(bx1[sp], by1[sp], bx2[sp], by2[sp])
                          : make_float4(0.f, 0.f, 0.f, 0.f);
        ((float4*)o_box)[b * MAX_DET + tid] = bb;
        o_cl[b * MAX_DET + tid] = valid ? (float)scls[sp] : 0.f;
    }
    if (tid == 0) o_num[b] = (float)ndet;
}

// ---------------- launcher ----------------
extern "C" void kernel_launch(void* const* d_in, const int* in_sizes, int n_in,
                              void* d_out, int out_size)
{
    const float* p3 = (const float*)d_in[0];
    const float* p4 = (const float*)d_in[1];
    const float* p5 = (const float*)d_in[2];
    int B = in_sizes[0] / (NO * 80 * 80);
    if (B > B_MAX) B = B_MAX;

    dim3 g1((A_TOT + 255) / 256, B);
    decode_kernel<<<g1, 256>>>(p3, p4, p5);
    fused_post_kernel<<<B, 1024>>>((float*)d_out, B);
}